// round 16
// baseline (speedup 1.0000x reference)
#include <cuda_runtime.h>
#include <cuda_bf16.h>
#include <cuda_fp16.h>
#include <math_constants.h>

// ---------------------------------------------------------------------------
//   x -> nonzero list ; conv1 sparse scatter into c1 f32 NHWC (global)
//   pool1 3x3 s2 + bias + relu -> g_p1p packed padded fp16 (conv2 sIn layout)
//   conv2 5x5 32->64 fp16 mma + fused pool2, grid (512,2 yhalf,4 ocq) 3 blk/SM
//   conv3 3x3 64->128 fp16 mma + fused pool3+mean, grid (512,4 ocq) 3 blk/SM
//   fc 128->128 relu -> 5
//
// Packed pair layouts (uint = f16x2 of channels 2P,2P+1):
//  conv2 input (32ch, 16 pairs/px, stride 16): pos(P) = 4*(P&3) + (P>>2)
//  conv3 input (64ch, stride 32): pos(P) = (P&16) + 4*(P&3) + ((P>>2)&3)
//  B weights per oc-slice: uint4/lane = {B[j0].b0,b1, B[j1].b0,b1}
// Halo borders of g_p1p/g_p2p never written (zero-init persists).
// Pool splits never cross block boundaries.
//
// mma.m16n8k16.f16 (g=lane>>2, t=lane&3): A a0=(g,2t:2t+1) a1=(g+8,..)
//   a2=(g,2t+8:2t+9) a3=(g+8,..); B b0=B[2t:2t+1][g] b1=B[2t+8:2t+9][g];
//   C c0=(g,2t) c1=(g,2t+1) c2=(g+8,2t) c3=(g+8,2t+1)
// ---------------------------------------------------------------------------

#define NB 512
#define NIMG (NB * 4)

#define P1_STRIDE (35 * 35 * 16)        // 19600 uints per image
#define P2_STRIDE (17 * 17 * 32)        // 9248 uints per image

__device__ float  g_c1 [NB * 64 * 64 * 32];
__device__ __align__(16) unsigned g_p1p[NB * P1_STRIDE];
__device__ __align__(16) unsigned g_p2p[NB * P2_STRIDE];
__device__ float  g_avg[NB * 128];
__device__ int            g_nzcnt [NIMG];
__device__ unsigned short g_nzlist[NIMG * 256];
__device__ __align__(16) unsigned g_w2f[4 * 25 * 256];   // [ocq][tap][256]
__device__ __align__(16) unsigned g_w3f[4 * 9 * 1024];   // [ocq][tap][1024]

__device__ __forceinline__ unsigned packh2(float a, float b) {
    __half2 h = __floats2half2_rn(a, b);
    return *(unsigned*)&h;
}

__device__ __forceinline__ void mma_f16(float& c0, float& c1, float& c2, float& c3,
                                        unsigned a0, unsigned a1, unsigned a2, unsigned a3,
                                        unsigned b0, unsigned b1) {
    asm volatile("mma.sync.aligned.m16n8k16.row.col.f32.f16.f16.f32 "
                 "{%0,%1,%2,%3},{%4,%5,%6,%7},{%8,%9},{%0,%1,%2,%3};"
                 : "+f"(c0), "+f"(c1), "+f"(c2), "+f"(c3)
                 : "r"(a0), "r"(a1), "r"(a2), "r"(a3), "r"(b0), "r"(b1));
}

// ---------------------------------------------------------------------------
// Launch 1: raster (blocks < NIMG) + zero c1 + weight prep, one grid.
// ---------------------------------------------------------------------------
#define ZB1 65536
#define PB  ((25600 + 36864 + 255) / 256)
#define L1_GRID (NIMG + ZB1 + PB)

__global__ void k_setup(const int* __restrict__ x,
                        const float* __restrict__ w2, const float* __restrict__ w3) {
    int bi = blockIdx.x;
    int tid = threadIdx.x;
    if (bi >= NIMG) {
        int zb = bi - NIMG;
        if (zb < ZB1) {
            ((float4*)g_c1)[zb * 256 + tid] = make_float4(0.f, 0.f, 0.f, 0.f);
        } else {
            int i = (zb - ZB1) * 256 + tid;
            if (i < 25600) {
                int ocq = i / 6400; int r = i - ocq * 6400;
                int tap = r >> 8; int i2 = r & 255;
                int c = i2 & 3, ln = (i2 >> 2) & 31, ks = (i2 >> 7) & 1;
                int h = c & 1, jpar = c >> 1;
                int tt = ln & 3, gg = ln >> 2;
                int k = ks * 16 + 2 * tt + 8 * h;
                int n = ocq * 16 + jpar * 8 + gg;
                g_w2f[i] = packh2(w2[n * 800 + k * 25 + tap],
                                  w2[n * 800 + (k + 1) * 25 + tap]);
            } else if (i < 25600 + 36864) {
                int ii = i - 25600;
                int ocq = ii / 9216; int r = ii - ocq * 9216;
                int tap = r >> 10; int i2 = r & 1023;
                int c = i2 & 3, ln = (i2 >> 2) & 31, jp = (i2 >> 7) & 1, ks = (i2 >> 8) & 3;
                int h = c & 1, jpar = c >> 1;
                int tt = ln & 3, gg = ln >> 2;
                int k = ks * 16 + 2 * tt + 8 * h;
                int oc = ocq * 32 + (2 * jp + jpar) * 8 + gg;
                g_w3f[ii] = packh2(w3[oc * 576 + k * 9 + tap],
                                   w3[oc * 576 + (k + 1) * 9 + tap]);
            }
        }
        return;
    }
    int img = bi;
    __shared__ int ax[9], ay[9];
    __shared__ int sdX, sloX, shiX, sloY, shiY;
    __shared__ int sCnt;
    __shared__ unsigned short sList[256];
    if (tid < 9) {
        int vx = x[img * 20 + tid * 2 + 0];
        int vy = x[img * 20 + tid * 2 + 1];
        ax[tid] = ((vx + 64) % 127 + 127) % 127;
        ay[tid] = ((64 - vy) % 127 + 127) % 127;
    }
    if (tid == 9) {
        int vx = x[img * 20 + 18];
        int vy = x[img * 20 + 19];
        int dX = 64 + vx, dY = 64 - vy;
        sdX = dX;
        sloX = (dX >= 64) ? 64 : dX + 1;
        shiX = (dX >= 64) ? dX - 1 : 64;
        sloY = (dY >= 64) ? 64 : dY + 1;
        shiY = (dY >= 64) ? dY - 1 : 64;
    }
    if (tid == 10) sCnt = 0;
    __syncthreads();
    for (int p = tid; p < 16384; p += blockDim.x) {
        int y = p >> 7, xx = p & 127;
        float val = 0.f;
        if (y == 64 && xx >= sloX && xx <= shiX) val = -1.f;
        if (xx == sdX && y >= sloY && y <= shiY) val = -1.f;
        if (y >= 63 && y <= 65 && xx >= 63 && xx <= 65)
            val = (y == 64 && xx == 64) ? 1.f : 0.5f;
        #pragma unroll
        for (int k = 0; k < 9; k++) {
            int dy = y - ay[k], dx = xx - ax[k];
            if (dy >= -1 && dy <= 1 && dx >= -1 && dx <= 1)
                val = (dy == 0 && dx == 0) ? 1.f : 0.5f;
        }
        if (val != 0.f) {
            int pos = atomicAdd(&sCnt, 1);
            if (pos < 256) {
                int code = (val == 0.5f) ? 0 : ((val == 1.f) ? 1 : 2);
                sList[pos] = (unsigned short)(p | (code << 14));
            }
        }
    }
    __syncthreads();
    int cnt = sCnt < 256 ? sCnt : 256;
    if (tid == 0) g_nzcnt[img] = cnt;
    for (int i = tid; i < cnt; i += blockDim.x)
        g_nzlist[img * 256 + i] = sList[i];
}

// ---------------------------------------------------------------------------
// Launch 2: sparse conv1 scatter (f32 atomics into NHWC c1).
// ---------------------------------------------------------------------------
__global__ void k_scatter1(const float* __restrict__ w1) {
    int img = blockIdx.x;
    int b = img >> 2, ci = img & 3;
    __shared__ float sW[49 * 32];
    __shared__ unsigned short sList[256];
    __shared__ int sCnt;
    int tid = threadIdx.x;
    for (int i = tid; i < 49 * 32; i += 256) {
        int oc = i & 31; int r = i >> 5;
        int ky = r / 7, kx = r % 7;
        sW[i] = w1[((oc * 4 + ci) * 7 + ky) * 7 + kx];
    }
    if (tid == 0) sCnt = g_nzcnt[img];
    __syncthreads();
    int cnt = sCnt;
    for (int i = tid; i < cnt; i += 256) sList[i] = g_nzlist[img * 256 + i];
    __syncthreads();
    int warp = tid >> 5, lane = tid & 31;
    for (int e = warp; e < cnt; e += 8) {
        int ent = sList[e];
        int p = ent & 16383, code = ent >> 14;
        float v = (code == 0) ? 0.5f : ((code == 1) ? 1.0f : -1.0f);
        int iy = p >> 7, ix = p & 127;
        #pragma unroll
        for (int ky = 0; ky < 7; ky++) {
            int t = iy + 3 - ky;
            if (t < 0 || t >= 128 || (t & 1)) continue;
            int oy = t >> 1;
            #pragma unroll
            for (int kx = 0; kx < 7; kx++) {
                int u = ix + 3 - kx;
                if (u < 0 || u >= 128 || (u & 1)) continue;
                int ox = u >> 1;
                atomicAdd(&g_c1[((b * 64 + oy) * 64 + ox) * 32 + lane],
                          v * sW[(ky * 7 + kx) * 32 + lane]);
            }
        }
    }
}

// ---------------------------------------------------------------------------
// Launch 3: pool1 -> packed padded fp16 (conv2 layout). pos = 4*(u&3)+(u>>2).
// ---------------------------------------------------------------------------
__global__ void k_pool1(const float* __restrict__ b1) {
    int idx = blockIdx.x * 256 + threadIdx.x;
    int u = idx & 15; int t2 = idx >> 4;
    int p = t2 % 961; int b = t2 / 961;
    int py = p / 31, px = p - py * 31;
    int oc0 = 2 * u;
    const float* ip = g_c1 + ((size_t)(b * 64 + 2 * py) * 64 + 2 * px) * 32 + oc0;
    float m0 = -CUDART_INF_F, m1 = -CUDART_INF_F;
    #pragma unroll
    for (int dy = 0; dy < 3; dy++)
        #pragma unroll
        for (int dx = 0; dx < 3; dx++) {
            float2 v = *(const float2*)&ip[(dy * 64 + dx) * 32];
            m0 = fmaxf(m0, v.x); m1 = fmaxf(m1, v.y);
        }
    float2 bb = *(const float2*)&b1[oc0];
    m0 = fmaxf(m0 + bb.x, 0.f); m1 = fmaxf(m1 + bb.y, 0.f);
    int pos = 4 * (u & 3) + (u >> 2);
    g_p1p[b * P1_STRIDE + ((py + 2) * 35 + px + 2) * 16 + pos] = packh2(m0, m1);
}

// ---------------------------------------------------------------------------
// Launch 4 (PROFILED): conv2 fp16 mma + fused pool2.
// grid (512, 2 yhalves, 4 oc-quarters). 8 warps x 64 px x 16 oc. 3 blk/SM.
// ---------------------------------------------------------------------------
#define C2_SINU  (21 * 35 * 16)                     // 11760 uints
#define C2_WFU   (25 * 256)                         // 6400 uints
#define C2_SMEM  ((C2_SINU + C2_WFU) * 4)           // 72640 B

extern __shared__ unsigned smem_u[];

__global__ __launch_bounds__(256, 3) void k_conv2_mma(const float* __restrict__ b2) {
    unsigned* sIn = smem_u;
    unsigned* wf  = smem_u + C2_SINU;
    int b = blockIdx.x;
    int y0 = blockIdx.y * 16;
    int ocq = blockIdx.z;
    int tid = threadIdx.x;
    int warp = tid >> 5, lane = tid & 31;
    int g = lane >> 2, t = lane & 3;

    {
        const uint4* ss = (const uint4*)(g_p1p + (size_t)b * P1_STRIDE + y0 * 35 * 16);
        uint4* sd = (uint4*)sIn;
        int navail = (35 - y0) * 35 * 4;
        for (int i = tid; i < C2_SINU / 4; i += 256)
            sd[i] = (i < navail) ? ss[i] : make_uint4(0u, 0u, 0u, 0u);
        const uint4* ws = (const uint4*)(g_w2f + ocq * C2_WFU);
        uint4* wd = (uint4*)wf;
        for (int i = tid; i < C2_WFU / 4; i += 256) wd[i] = ws[i];
    }
    __syncthreads();

    int p0 = warp * 64;
    int plr[8], plx[8], abase[8];
    #pragma unroll
    for (int mt = 0; mt < 4; mt++)
        #pragma unroll
        for (int h = 0; h < 2; h++) {
            int i = mt * 2 + h;
            int p = p0 + mt * 16 + g + h * 8;       // 0..511 local
            int pyl = p / 31, px = p - pyl * 31;
            plr[i] = pyl; plx[i] = px;
            abase[i] = (pyl * 35 + px) * 16 + 4 * t;
        }

    float acc[4][2][4];
    #pragma unroll
    for (int mt = 0; mt < 4; mt++)
        #pragma unroll
        for (int j = 0; j < 2; j++)
            #pragma unroll
            for (int q = 0; q < 4; q++) acc[mt][j][q] = 0.f;

    #pragma unroll 1
    for (int tap = 0; tap < 25; tap++) {
        const unsigned* cur = wf + tap * 256;
        int ky = tap / 5, kx = tap - ky * 5;
        int toff = (ky * 35 + kx) * 16;
        uint4 Ar[8];
        #pragma unroll
        for (int i = 0; i < 8; i++)
            Ar[i] = *(const uint4*)&sIn[abase[i] + toff];
        #pragma unroll
        for (int ks = 0; ks < 2; ks++) {
            uint4 Bq = *(const uint4*)&cur[(ks * 32 + lane) * 4];
            #pragma unroll
            for (int mt = 0; mt < 4; mt++) {
                unsigned a0 = ks ? Ar[2 * mt].z     : Ar[2 * mt].x;
                unsigned a2 = ks ? Ar[2 * mt].w     : Ar[2 * mt].y;
                unsigned a1 = ks ? Ar[2 * mt + 1].z : Ar[2 * mt + 1].x;
                unsigned a3 = ks ? Ar[2 * mt + 1].w : Ar[2 * mt + 1].y;
                mma_f16(acc[mt][0][0], acc[mt][0][1], acc[mt][0][2], acc[mt][0][3],
                        a0, a1, a2, a3, Bq.x, Bq.y);
                mma_f16(acc[mt][1][0], acc[mt][1][1], acc[mt][1][2], acc[mt][1][3],
                        a0, a1, a2, a3, Bq.z, Bq.w);
            }
        }
    }

    // ---- Fused epilogue: stash tile in smem, pool 2x2 s2 -> g_p2p ----
    __syncthreads();
    unsigned* sc2 = smem_u;                          // [16 rows][31 px][8 pairs]
    int rowlim = (31 - y0 < 16) ? (31 - y0) : 16;
    #pragma unroll
    for (int j = 0; j < 2; j++) {
        int jj = j * 4 + t;                          // local pair 0..7
        float2 bb = *(const float2*)&b2[ocq * 16 + 2 * jj];
        #pragma unroll
        for (int mt = 0; mt < 4; mt++) {
            int ilo = mt * 2, ihi = mt * 2 + 1;
            if (plr[ilo] < rowlim)
                sc2[(plr[ilo] * 31 + plx[ilo]) * 8 + jj] =
                    packh2(fmaxf(acc[mt][j][0] + bb.x, 0.f),
                           fmaxf(acc[mt][j][1] + bb.y, 0.f));
            if (plr[ihi] < rowlim)
                sc2[(plr[ihi] * 31 + plx[ihi]) * 8 + jj] =
                    packh2(fmaxf(acc[mt][j][2] + bb.x, 0.f),
                           fmaxf(acc[mt][j][3] + bb.y, 0.f));
        }
    }
    __syncthreads();
    int npool = (y0 == 0) ? 8 : 7;
    for (int i = tid; i < npool * 15 * 8; i += 256) {
        int jj = i & 7; int r = i >> 3;
        int px = r % 15; int pyl2 = r / 15;
        const __half2* s = (const __half2*)&sc2[((2 * pyl2) * 31 + 2 * px) * 8 + jj];
        __half2 m = __hmax2(__hmax2(s[0], s[8]), __hmax2(s[31 * 8], s[31 * 8 + 8]));
        int pyp = (y0 == 0) ? pyl2 : (8 + pyl2);
        int P = ocq * 8 + jj;
        int pos = (P & 16) + 4 * (P & 3) + ((P >> 2) & 3);
        g_p2p[b * P2_STRIDE + ((pyp + 1) * 17 + px + 1) * 32 + pos] = *(unsigned*)&m;
    }
}

// ---------------------------------------------------------------------------
// Launch 5: conv3 fp16 mma + fused pool3+mean. grid (512, 4 oc-quarters),
// 8 warps x 32 px x 32 oc. 3 blocks/SM. Writes g_avg directly.
// ---------------------------------------------------------------------------
#define C3_SINU  P2_STRIDE                          // 9248 uints
#define C3_WFU   (9 * 1024)                         // 9216 uints
#define C3_SMEM  ((C3_SINU + C3_WFU) * 4)           // 73856 B

__global__ __launch_bounds__(256, 3) void k_conv3_mma(const float* __restrict__ b3) {
    unsigned* sIn = smem_u;
    unsigned* wf  = smem_u + C3_SINU;
    int b = blockIdx.x;
    int ocq = blockIdx.y;
    int tid = threadIdx.x;
    int warp = tid >> 5, lane = tid & 31;
    int g = lane >> 2, t = lane & 3;

    {
        const uint4* ss = (const uint4*)(g_p2p + (size_t)b * P2_STRIDE);
        uint4* sd = (uint4*)sIn;
        for (int i = tid; i < C3_SINU / 4; i += 256) sd[i] = ss[i];
        const uint4* ws = (const uint4*)(g_w3f + ocq * C3_WFU);
        uint4* wd = (uint4*)wf;
        for (int i = tid; i < C3_WFU / 4; i += 256) wd[i] = ws[i];
    }
    __syncthreads();

    int p0 = warp * 32;
    int prow[4], abase[4];
    #pragma unroll
    for (int mt = 0; mt < 2; mt++)
        #pragma unroll
        for (int h = 0; h < 2; h++) {
            int i = mt * 2 + h;
            int p = p0 + mt * 16 + g + h * 8;
            int py = p / 15, px = p - py * 15;
            prow[i] = p;
            abase[i] = (py * 17 + px) * 32 + 4 * t;
        }

    float acc[2][4][4];
    #pragma unroll
    for (int mt = 0; mt < 2; mt++)
        #pragma unroll
        for (int j = 0; j < 4; j++)
            #pragma unroll
            for (int q = 0; q < 4; q++) acc[mt][j][q] = 0.f;

    #pragma unroll 1
    for (int tap = 0; tap < 9; tap++) {
        const unsigned* cur = wf + tap * 1024;
        int ky = tap / 3, kx = tap - ky * 3;
        int toff = (ky * 17 + kx) * 32;
        #pragma unroll
        for (int kk = 0; kk < 2; kk++) {
            uint4 Ar[4];
            #pragma unroll
            for (int i = 0; i < 4; i++)
                Ar[i] = *(const uint4*)&sIn[abase[i] + toff + 16 * kk];
            #pragma unroll
            for (int ks2 = 0; ks2 < 2; ks2++) {
                int ks = kk * 2 + ks2;
                #pragma unroll
                for (int jp = 0; jp < 2; jp++) {
                    uint4 Bq = *(const uint4*)&cur[((ks * 2 + jp) * 32 + lane) * 4];
                    #pragma unroll
                    for (int mt = 0; mt < 2; mt++) {
                        unsigned a0 = ks2 ? Ar[2 * mt].z     : Ar[2 * mt].x;
                        unsigned a2 = ks2 ? Ar[2 * mt].w     : Ar[2 * mt].y;
                        unsigned a1 = ks2 ? Ar[2 * mt + 1].z : Ar[2 * mt + 1].x;
                        unsigned a3 = ks2 ? Ar[2 * mt + 1].w : Ar[2 * mt + 1].y;
                        mma_f16(acc[mt][2 * jp][0], acc[mt][2 * jp][1],
                                acc[mt][2 * jp][2], acc[mt][2 * jp][3],
                                a0, a1, a2, a3, Bq.x, Bq.y);
                        mma_f16(acc[mt][2 * jp + 1][0], acc[mt][2 * jp + 1][1],
                                acc[mt][2 * jp + 1][2], acc[mt][2 * jp + 1][3],
                                a0, a1, a2, a3, Bq.z, Bq.w);
                    }
                }
            }
        }
    }

    // ---- Fused epilogue: stash tile, pool 2x2 s2 (15->7) + mean -> g_avg ----
    __syncthreads();
    unsigned* sc3 = smem_u;                          // [225][16 pairs]
    float* sred = (float*)(smem_u + 3616);           // [7][16 pairs][2]
    #pragma unroll
    for (int j = 0; j < 4; j++) {
        int jj = j * 4 + t;                          // local pair 0..15
        float2 bb = *(const float2*)&b3[ocq * 32 + 2 * jj];
        #pragma unroll
        for (int mt = 0; mt < 2; mt++) {
            int plo = prow[mt * 2], phi = prow[mt * 2 + 1];
            if (plo < 225)
                sc3[plo * 16 + jj] = packh2(fmaxf(acc[mt][j][0] + bb.x, 0.f),
                                            fmaxf(acc[mt][j][1] + bb.y, 0.f));
            if (phi < 225)
                sc3[phi * 16 + jj] = packh2(fmaxf(acc[mt][j][2] + bb.x, 0.f),
                                            fmaxf(acc[mt][j][3] + bb.y, 0.f));
        }
    }
    __syncthreads();
    if (tid < 112) {
        int pair = tid & 15, py = tid >> 4;          // py 0..6
        float s0 = 0.f, s1 = 0.f;
        #pragma unroll
        for (int px = 0; px < 7; px++) {
            const __half2* s = (const __half2*)&sc3[((2 * py) * 15 + 2 * px) * 16 + pair];
            __half2 m = __hmax2(__hmax2(s[0], s[16]), __hmax2(s[15 * 16], s[15 * 16 + 16]));
            float2 f = __half22float2(m);
            s0 += f.x; s1 += f.y;
        }
        sred[(py * 16 + pair) * 2]     = s0;
        sred[(py * 16 + pair) * 2 + 1] = s1;
    }
    __syncthreads();
    if (tid < 16) {
        float s0 = 0.f, s1 = 0.f;
        #pragma unroll
        for (int py = 0; py < 7; py++) {
            s0 += sred[(py * 16 + tid) * 2];
            s1 += sred[(py * 16 + tid) * 2 + 1];
        }
        g_avg[b * 128 + ocq * 32 + 2 * tid]     = s0 * (1.f / 49.f);
        g_avg[b * 128 + ocq * 32 + 2 * tid + 1] = s1 * (1.f / 49.f);
    }
}

// ---------------------------------------------------------------------------
// Launch 6: FC 128 -> 128 relu -> 5
// ---------------------------------------------------------------------------
__global__ void k_fc(const float* __restrict__ fw1, const float* __restrict__ fb1,
                     const float* __restrict__ fw2, const float* __restrict__ fb2,
                     float* __restrict__ out) {
    int b = blockIdx.x;
    int tid = threadIdx.x;
    __shared__ float sa[128], sh[128];
    sa[tid] = g_avg[b * 128 + tid];
    __syncthreads();
    float s = fb1[tid];
    const float* wr = fw1 + tid * 128;
    #pragma unroll 8
    for (int j = 0; j < 128; j++) s += wr[j] * sa[j];
    sh[tid] = s > 0.f ? s : 0.f;
    __syncthreads();
    if (tid < 5) {
        float o = fb2[tid];
        const float* wr2 = fw2 + tid * 128;
        #pragma unroll 8
        for (int j = 0; j < 128; j++) o += wr2[j] * sh[j];
        out[b * 5 + tid] = o;
    }
}

// ---------------------------------------------------------------------------
extern "C" void kernel_launch(void* const* d_in, const int* in_sizes, int n_in,
                              void* d_out, int out_size) {
    const int*   x   = (const int*)  d_in[0];
    const float* w1  = (const float*)d_in[1];
    const float* b1  = (const float*)d_in[2];
    const float* w2  = (const float*)d_in[3];
    const float* b2  = (const float*)d_in[4];
    const float* w3  = (const float*)d_in[5];
    const float* b3  = (const float*)d_in[6];
    const float* fw1 = (const float*)d_in[7];
    const float* fb1 = (const float*)d_in[8];
    const float* fw2 = (const float*)d_in[9];
    const float* fb2 = (const float*)d_in[10];
    float* out = (float*)d_out;

    cudaFuncSetAttribute(k_conv2_mma, cudaFuncAttributeMaxDynamicSharedMemorySize, C2_SMEM);
    cudaFuncSetAttribute(k_conv3_mma, cudaFuncAttributeMaxDynamicSharedMemorySize, C3_SMEM);

    k_setup<<<L1_GRID, 256>>>(x, w2, w3);                       // 1
    k_scatter1<<<NIMG, 256>>>(w1);                              // 2
    k_pool1<<<(NB * 961 * 16) / 256, 256>>>(b1);                // 3
    k_conv2_mma<<<dim3(NB, 2, 4), 256, C2_SMEM>>>(b2);          // 4 <- profiled
    k_conv3_mma<<<dim3(NB, 4), 256, C3_SMEM>>>(b3);             // 5
    k_fc<<<NB, 128>>>(fw1, fb1, fw2, fb2, out);                 // 6
}

// round 17
// speedup vs baseline: 1.1307x; 1.1307x over previous
#include <cuda_runtime.h>
#include <cuda_bf16.h>
#include <cuda_fp16.h>
#include <math_constants.h>

// ---------------------------------------------------------------------------
//   x -> nonzero list ; conv1 sparse scatter into c1 FP16 NHWC (half2 atomics)
//   pool1 3x3 s2 + bias + relu -> g_p1p packed padded fp16 (conv2 sIn layout)
//   conv2 5x5 32->64 fp16 mma + fused pool2, grid (512,2 yhalf,2 ochalf) 2 blk/SM
//   conv3 3x3 64->128 fp16 mma + fused pool3+mean, grid (512,2 ochalf) 2 blk/SM
//   fc 128->128 relu -> 5
//
// Packed pair layouts (uint = f16x2 of channels 2P,2P+1):
//  conv2 input (32ch, 16 pairs/px, stride 16): pos(P) = 4*(P&3) + (P>>2)
//  conv3 input (64ch, stride 32): pos(P) = (P&16) + 4*(P&3) + ((P>>2)&3)
//  B weights: uint4 per lane = {B[2jp].b0,b1, B[2jp+1].b0,b1}, per oc-half.
// Halo borders of g_p1p/g_p2p never written (zero-init persists).
// Pool splits never cross block boundaries.
//
// mma.m16n8k16.f16 (g=lane>>2, t=lane&3): A a0=(g,2t:2t+1) a1=(g+8,..)
//   a2=(g,2t+8:2t+9) a3=(g+8,..); B b0=B[2t:2t+1][g] b1=B[2t+8:2t+9][g];
//   C c0=(g,2t) c1=(g,2t+1) c2=(g+8,2t) c3=(g+8,2t+1)
// ---------------------------------------------------------------------------

#define NB 512
#define NIMG (NB * 4)

#define P1_STRIDE (35 * 35 * 16)        // 19600 uints per image
#define P2_STRIDE (17 * 17 * 32)        // 9248 uints per image

__device__ __align__(16) __half g_c1h[NB * 64 * 64 * 32];   // fp16 NHWC (half2 atomics)
__device__ __align__(16) unsigned g_p1p[NB * P1_STRIDE];
__device__ __align__(16) unsigned g_p2p[NB * P2_STRIDE];
__device__ float  g_avg[NB * 128];
__device__ int            g_nzcnt [NIMG];
__device__ unsigned short g_nzlist[NIMG * 256];
__device__ __align__(16) unsigned g_w2f[2 * 25 * 512];   // [ochalf][tap][512]
__device__ __align__(16) unsigned g_w3f[2 * 9 * 2048];   // [ochalf][tap][2048]

__device__ __forceinline__ unsigned packh2(float a, float b) {
    __half2 h = __floats2half2_rn(a, b);
    return *(unsigned*)&h;
}

__device__ __forceinline__ void mma_f16(float& c0, float& c1, float& c2, float& c3,
                                        unsigned a0, unsigned a1, unsigned a2, unsigned a3,
                                        unsigned b0, unsigned b1) {
    asm volatile("mma.sync.aligned.m16n8k16.row.col.f32.f16.f16.f32 "
                 "{%0,%1,%2,%3},{%4,%5,%6,%7},{%8,%9},{%0,%1,%2,%3};"
                 : "+f"(c0), "+f"(c1), "+f"(c2), "+f"(c3)
                 : "r"(a0), "r"(a1), "r"(a2), "r"(a3), "r"(b0), "r"(b1));
}

// ---------------------------------------------------------------------------
// Launch 1: raster (blocks < NIMG) + zero c1 (fp16) + weight prep, one grid.
// ---------------------------------------------------------------------------
#define ZB1 32768                                   // 67.1M halves / 8 / 256
#define PB  ((25600 + 36864 + 255) / 256)
#define L1_GRID (NIMG + ZB1 + PB)

__global__ void k_setup(const int* __restrict__ x,
                        const float* __restrict__ w2, const float* __restrict__ w3) {
    int bi = blockIdx.x;
    int tid = threadIdx.x;
    if (bi >= NIMG) {
        int zb = bi - NIMG;
        if (zb < ZB1) {
            ((uint4*)g_c1h)[zb * 256 + tid] = make_uint4(0u, 0u, 0u, 0u);
        } else {
            int i = (zb - ZB1) * 256 + tid;
            if (i < 25600) {
                int half = i / 12800; int r = i - half * 12800;
                int tap = r >> 9; int i2 = r & 511;
                int c = i2 & 3, ln = (i2 >> 2) & 31, jp = (i2 >> 7) & 1, ks = (i2 >> 8) & 1;
                int h = c & 1, jpar = c >> 1;
                int tt = ln & 3, gg = ln >> 2;
                int k = ks * 16 + 2 * tt + 8 * h;
                int n = half * 32 + (2 * jp + jpar) * 8 + gg;
                g_w2f[i] = packh2(w2[n * 800 + k * 25 + tap],
                                  w2[n * 800 + (k + 1) * 25 + tap]);
            } else if (i < 25600 + 36864) {
                int ii = i - 25600;
                int half = ii / 18432; int r = ii - half * 18432;
                int tap = r >> 11; int i2 = r & 2047;
                int c = i2 & 3, ln = (i2 >> 2) & 31, jp = (i2 >> 7) & 3, ks = (i2 >> 9) & 3;
                int h = c & 1, jpar = c >> 1;
                int tt = ln & 3, gg = ln >> 2;
                int k = ks * 16 + 2 * tt + 8 * h;
                int oc = half * 64 + (2 * jp + jpar) * 8 + gg;
                g_w3f[ii] = packh2(w3[oc * 576 + k * 9 + tap],
                                   w3[oc * 576 + (k + 1) * 9 + tap]);
            }
        }
        return;
    }
    int img = bi;
    __shared__ int ax[9], ay[9];
    __shared__ int sdX, sloX, shiX, sloY, shiY;
    __shared__ int sCnt;
    __shared__ unsigned short sList[256];
    if (tid < 9) {
        int vx = x[img * 20 + tid * 2 + 0];
        int vy = x[img * 20 + tid * 2 + 1];
        ax[tid] = ((vx + 64) % 127 + 127) % 127;
        ay[tid] = ((64 - vy) % 127 + 127) % 127;
    }
    if (tid == 9) {
        int vx = x[img * 20 + 18];
        int vy = x[img * 20 + 19];
        int dX = 64 + vx, dY = 64 - vy;
        sdX = dX;
        sloX = (dX >= 64) ? 64 : dX + 1;
        shiX = (dX >= 64) ? dX - 1 : 64;
        sloY = (dY >= 64) ? 64 : dY + 1;
        shiY = (dY >= 64) ? dY - 1 : 64;
    }
    if (tid == 10) sCnt = 0;
    __syncthreads();
    for (int p = tid; p < 16384; p += blockDim.x) {
        int y = p >> 7, xx = p & 127;
        float val = 0.f;
        if (y == 64 && xx >= sloX && xx <= shiX) val = -1.f;
        if (xx == sdX && y >= sloY && y <= shiY) val = -1.f;
        if (y >= 63 && y <= 65 && xx >= 63 && xx <= 65)
            val = (y == 64 && xx == 64) ? 1.f : 0.5f;
        #pragma unroll
        for (int k = 0; k < 9; k++) {
            int dy = y - ay[k], dx = xx - ax[k];
            if (dy >= -1 && dy <= 1 && dx >= -1 && dx <= 1)
                val = (dy == 0 && dx == 0) ? 1.f : 0.5f;
        }
        if (val != 0.f) {
            int pos = atomicAdd(&sCnt, 1);
            if (pos < 256) {
                int code = (val == 0.5f) ? 0 : ((val == 1.f) ? 1 : 2);
                sList[pos] = (unsigned short)(p | (code << 14));
            }
        }
    }
    __syncthreads();
    int cnt = sCnt < 256 ? sCnt : 256;
    if (tid == 0) g_nzcnt[img] = cnt;
    for (int i = tid; i < cnt; i += blockDim.x)
        g_nzlist[img * 256 + i] = sList[i];
}

// ---------------------------------------------------------------------------
// Launch 2: sparse conv1 scatter (half2 atomics into fp16 NHWC c1).
// Half-warp per entry: lanes 0-15 / 16-31 take entries warp*2 / warp*2+1;
// lane p16 covers oc pair (2*p16, 2*p16+1).
// ---------------------------------------------------------------------------
__global__ void k_scatter1(const float* __restrict__ w1) {
    int img = blockIdx.x;
    int b = img >> 2, ci = img & 3;
    __shared__ float sW[49 * 32];
    __shared__ unsigned short sList[256];
    __shared__ int sCnt;
    int tid = threadIdx.x;
    for (int i = tid; i < 49 * 32; i += 256) {
        int oc = i & 31; int r = i >> 5;
        int ky = r / 7, kx = r % 7;
        sW[i] = w1[((oc * 4 + ci) * 7 + ky) * 7 + kx];
    }
    if (tid == 0) sCnt = g_nzcnt[img];
    __syncthreads();
    int cnt = sCnt;
    for (int i = tid; i < cnt; i += 256) sList[i] = g_nzlist[img * 256 + i];
    __syncthreads();
    int warp = tid >> 5, lane = tid & 31;
    int ehalf = lane >> 4, p16 = lane & 15;
    for (int e = warp * 2 + ehalf; e < cnt; e += 16) {
        int ent = sList[e];
        int p = ent & 16383, code = ent >> 14;
        float v = (code == 0) ? 0.5f : ((code == 1) ? 1.0f : -1.0f);
        int iy = p >> 7, ix = p & 127;
        #pragma unroll
        for (int ky = 0; ky < 7; ky++) {
            int t = iy + 3 - ky;
            if (t < 0 || t >= 128 || (t & 1)) continue;
            int oy = t >> 1;
            #pragma unroll
            for (int kx = 0; kx < 7; kx++) {
                int u = ix + 3 - kx;
                if (u < 0 || u >= 128 || (u & 1)) continue;
                int ox = u >> 1;
                const float* wp = &sW[(ky * 7 + kx) * 32 + 2 * p16];
                __half2 hv = __floats2half2_rn(v * wp[0], v * wp[1]);
                atomicAdd((__half2*)&g_c1h[((size_t)(b * 64 + oy) * 64 + ox) * 32 + 2 * p16], hv);
            }
        }
    }
}

// ---------------------------------------------------------------------------
// Launch 3: pool1 (fp16 in) -> packed padded fp16 (conv2 layout).
// pair u 0..15, pos = 4*(u&3)+(u>>2).
// ---------------------------------------------------------------------------
__global__ void k_pool1(const float* __restrict__ b1) {
    int idx = blockIdx.x * 256 + threadIdx.x;
    int u = idx & 15; int t2 = idx >> 4;
    int p = t2 % 961; int b = t2 / 961;
    int py = p / 31, px = p - py * 31;
    const __half2* ip = (const __half2*)g_c1h + ((size_t)(b * 64 + 2 * py) * 64 + 2 * px) * 16 + u;
    __half2 m = __float2half2_rn(-60000.f);
    #pragma unroll
    for (int dy = 0; dy < 3; dy++)
        #pragma unroll
        for (int dx = 0; dx < 3; dx++)
            m = __hmax2(m, ip[(dy * 64 + dx) * 16]);
    float2 f = __half22float2(m);
    float2 bb = *(const float2*)&b1[2 * u];
    float m0 = fmaxf(f.x + bb.x, 0.f), m1 = fmaxf(f.y + bb.y, 0.f);
    int pos = 4 * (u & 3) + (u >> 2);
    g_p1p[b * P1_STRIDE + ((py + 2) * 35 + px + 2) * 16 + pos] = packh2(m0, m1);
}

// ---------------------------------------------------------------------------
// Launch 4 (PROFILED): conv2 fp16 mma + fused pool2.
// grid (512, 2 yhalves, 2 oc-halves). 8 warps x 64 px x 32 oc. 2 blk/SM.
// ---------------------------------------------------------------------------
#define C2_SINU  (21 * 35 * 16)                     // 11760 uints
#define C2_WFU   (25 * 512)                         // 12800 uints
#define C2_SMEM  ((C2_SINU + C2_WFU) * 4)           // 98240 B

extern __shared__ unsigned smem_u[];

__global__ __launch_bounds__(256, 2) void k_conv2_mma(const float* __restrict__ b2) {
    unsigned* sIn = smem_u;
    unsigned* wf  = smem_u + C2_SINU;
    int b = blockIdx.x;
    int y0 = blockIdx.y * 16;
    int ochalf = blockIdx.z;
    int tid = threadIdx.x;
    int warp = tid >> 5, lane = tid & 31;
    int g = lane >> 2, t = lane & 3;

    {
        const uint4* ss = (const uint4*)(g_p1p + (size_t)b * P1_STRIDE + y0 * 35 * 16);
        uint4* sd = (uint4*)sIn;
        int navail = (35 - y0) * 35 * 4;
        for (int i = tid; i < C2_SINU / 4; i += 256)
            sd[i] = (i < navail) ? ss[i] : make_uint4(0u, 0u, 0u, 0u);
        const uint4* ws = (const uint4*)(g_w2f + ochalf * C2_WFU);
        uint4* wd = (uint4*)wf;
        for (int i = tid; i < C2_WFU / 4; i += 256) wd[i] = ws[i];
    }
    __syncthreads();

    int p0 = warp * 64;
    int plr[8], plx[8], abase[8];
    #pragma unroll
    for (int mt = 0; mt < 4; mt++)
        #pragma unroll
        for (int h = 0; h < 2; h++) {
            int i = mt * 2 + h;
            int p = p0 + mt * 16 + g + h * 8;       // 0..511 local
            int pyl = p / 31, px = p - pyl * 31;
            plr[i] = pyl; plx[i] = px;
            abase[i] = (pyl * 35 + px) * 16 + 4 * t;
        }

    float acc[4][4][4];
    #pragma unroll
    for (int mt = 0; mt < 4; mt++)
        #pragma unroll
        for (int j = 0; j < 4; j++)
            #pragma unroll
            for (int q = 0; q < 4; q++) acc[mt][j][q] = 0.f;

    #pragma unroll 1
    for (int tap = 0; tap < 25; tap++) {
        const unsigned* cur = wf + tap * 512;
        int ky = tap / 5, kx = tap - ky * 5;
        int toff = (ky * 35 + kx) * 16;
        uint4 Ar[8];
        #pragma unroll
        for (int i = 0; i < 8; i++)
            Ar[i] = *(const uint4*)&sIn[abase[i] + toff];
        #pragma unroll
        for (int ks = 0; ks < 2; ks++) {
            uint4 Bq[2];
            #pragma unroll
            for (int jp = 0; jp < 2; jp++)
                Bq[jp] = *(const uint4*)&cur[((ks * 2 + jp) * 32 + lane) * 4];
            #pragma unroll
            for (int mt = 0; mt < 4; mt++) {
                unsigned a0 = ks ? Ar[2 * mt].z     : Ar[2 * mt].x;
                unsigned a2 = ks ? Ar[2 * mt].w     : Ar[2 * mt].y;
                unsigned a1 = ks ? Ar[2 * mt + 1].z : Ar[2 * mt + 1].x;
                unsigned a3 = ks ? Ar[2 * mt + 1].w : Ar[2 * mt + 1].y;
                #pragma unroll
                for (int jp = 0; jp < 2; jp++) {
                    mma_f16(acc[mt][2 * jp][0], acc[mt][2 * jp][1],
                            acc[mt][2 * jp][2], acc[mt][2 * jp][3],
                            a0, a1, a2, a3, Bq[jp].x, Bq[jp].y);
                    mma_f16(acc[mt][2 * jp + 1][0], acc[mt][2 * jp + 1][1],
                            acc[mt][2 * jp + 1][2], acc[mt][2 * jp + 1][3],
                            a0, a1, a2, a3, Bq[jp].z, Bq[jp].w);
                }
            }
        }
    }

    // ---- Fused epilogue: stash c2 tile in smem, pool 2x2 s2 -> g_p2p ----
    __syncthreads();
    unsigned* sc2 = smem_u;                         // [row16][px31][pair16]
    int rowlim = (31 - y0 < 16) ? (31 - y0) : 16;
    #pragma unroll
    for (int j = 0; j < 4; j++) {
        int jj = j * 4 + t;                         // local oc pair 0..15
        float2 bb = *(const float2*)&b2[ochalf * 32 + 2 * jj];
        #pragma unroll
        for (int mt = 0; mt < 4; mt++) {
            int ilo = mt * 2, ihi = mt * 2 + 1;
            if (plr[ilo] < rowlim)
                sc2[(plr[ilo] * 31 + plx[ilo]) * 16 + jj] =
                    packh2(fmaxf(acc[mt][j][0] + bb.x, 0.f),
                           fmaxf(acc[mt][j][1] + bb.y, 0.f));
            if (plr[ihi] < rowlim)
                sc2[(plr[ihi] * 31 + plx[ihi]) * 16 + jj] =
                    packh2(fmaxf(acc[mt][j][2] + bb.x, 0.f),
                           fmaxf(acc[mt][j][3] + bb.y, 0.f));
        }
    }
    __syncthreads();
    int npool = (y0 == 0) ? 8 : 7;
    for (int i = tid; i < npool * 15 * 16; i += 256) {
        int jj = i & 15; int r = i >> 4;
        int px = r % 15; int pyl2 = r / 15;
        const __half2* s = (const __half2*)&sc2[((2 * pyl2) * 31 + 2 * px) * 16 + jj];
        __half2 m = __hmax2(__hmax2(s[0], s[16]), __hmax2(s[31 * 16], s[31 * 16 + 16]));
        int pyp = (y0 == 0) ? pyl2 : (8 + pyl2);
        int pos = ochalf * 16 + 4 * (jj & 3) + ((jj >> 2) & 3);
        g_p2p[b * P2_STRIDE + ((pyp + 1) * 17 + px + 1) * 32 + pos] = *(unsigned*)&m;
    }
}

// ---------------------------------------------------------------------------
// Launch 5: conv3 fp16 mma + fused pool3+mean. grid (512, 2 oc-halves),
// 8 warps x 32 px x 64 oc. 2 blocks/SM. Writes g_avg directly.
// ---------------------------------------------------------------------------
#define C3_SINU  P2_STRIDE                          // 9248 uints
#define C3_WFU   (9 * 2048)                         // 18432 uints
#define C3_SMEM  ((C3_SINU + C3_WFU) * 4)           // 110720 B

__global__ __launch_bounds__(256, 2) void k_conv3_mma(const float* __restrict__ b3) {
    unsigned* sIn = smem_u;
    unsigned* wf  = smem_u + C3_SINU;
    int b = blockIdx.x;
    int ochalf = blockIdx.y;
    int tid = threadIdx.x;
    int warp = tid >> 5, lane = tid & 31;
    int g = lane >> 2, t = lane & 3;

    {
        const uint4* ss = (const uint4*)(g_p2p + (size_t)b * P2_STRIDE);
        uint4* sd = (uint4*)sIn;
        for (int i = tid; i < C3_SINU / 4; i += 256) sd[i] = ss[i];
        const uint4* ws = (const uint4*)(g_w3f + ochalf * C3_WFU);
        uint4* wd = (uint4*)wf;
        for (int i = tid; i < C3_WFU / 4; i += 256) wd[i] = ws[i];
    }
    __syncthreads();

    int p0 = warp * 32;
    int prow[4], abase[4];
    #pragma unroll
    for (int mt = 0; mt < 2; mt++)
        #pragma unroll
        for (int h = 0; h < 2; h++) {
            int i = mt * 2 + h;
            int p = p0 + mt * 16 + g + h * 8;
            int py = p / 15, px = p - py * 15;
            prow[i] = p;
            abase[i] = (py * 17 + px) * 32 + 4 * t;
        }

    float acc[2][8][4];
    #pragma unroll
    for (int mt = 0; mt < 2; mt++)
        #pragma unroll
        for (int j = 0; j < 8; j++)
            #pragma unroll
            for (int q = 0; q < 4; q++) acc[mt][j][q] = 0.f;

    #pragma unroll 1
    for (int tap = 0; tap < 9; tap++) {
        const unsigned* cur = wf + tap * 2048;
        int ky = tap / 3, kx = tap - ky * 3;
        int toff = (ky * 17 + kx) * 32;
        #pragma unroll
        for (int kk = 0; kk < 2; kk++) {
            uint4 Ar[4];
            #pragma unroll
            for (int i = 0; i < 4; i++)
                Ar[i] = *(const uint4*)&sIn[abase[i] + toff + 16 * kk];
            #pragma unroll
            for (int ks2 = 0; ks2 < 2; ks2++) {
                int ks = kk * 2 + ks2;
                uint4 Bq[4];
                #pragma unroll
                for (int jp = 0; jp < 4; jp++)
                    Bq[jp] = *(const uint4*)&cur[((ks * 4 + jp) * 32 + lane) * 4];
                #pragma unroll
                for (int mt = 0; mt < 2; mt++) {
                    unsigned a0 = ks2 ? Ar[2 * mt].z     : Ar[2 * mt].x;
                    unsigned a2 = ks2 ? Ar[2 * mt].w     : Ar[2 * mt].y;
                    unsigned a1 = ks2 ? Ar[2 * mt + 1].z : Ar[2 * mt + 1].x;
                    unsigned a3 = ks2 ? Ar[2 * mt + 1].w : Ar[2 * mt + 1].y;
                    #pragma unroll
                    for (int jp = 0; jp < 4; jp++) {
                        mma_f16(acc[mt][2 * jp][0], acc[mt][2 * jp][1],
                                acc[mt][2 * jp][2], acc[mt][2 * jp][3],
                                a0, a1, a2, a3, Bq[jp].x, Bq[jp].y);
                        mma_f16(acc[mt][2 * jp + 1][0], acc[mt][2 * jp + 1][1],
                                acc[mt][2 * jp + 1][2], acc[mt][2 * jp + 1][3],
                                a0, a1, a2, a3, Bq[jp].z, Bq[jp].w);
                    }
                }
            }
        }
    }

    // ---- Fused epilogue: stash tile, pool 2x2 s2 (15->7) + mean -> g_avg ----
    __syncthreads();
    unsigned* sc3 = smem_u;                          // [225][32 pairs]
    float* sred = (float*)(smem_u + 7232);           // [7][32 pairs][2]
    #pragma unroll
    for (int j = 0; j < 8; j++) {
        int jj = j * 4 + t;                          // local oc pair 0..31
        float2 bb = *(const float2*)&b3[ochalf * 64 + 2 * jj];
        #pragma unroll
        for (int mt = 0; mt < 2; mt++) {
            int plo = prow[mt * 2], phi = prow[mt * 2 + 1];
            if (plo < 225)
                sc3[plo * 32 + jj] = packh2(fmaxf(acc[mt][j][0] + bb.x, 0.f),
                                            fmaxf(acc[mt][j][1] + bb.y, 0.f));
            if (phi < 225)
                sc3[phi * 32 + jj] = packh2(fmaxf(acc[mt][j][2] + bb.x, 0.f),
                                            fmaxf(acc[mt][j][3] + bb.y, 0.f));
        }
    }
    __syncthreads();
    if (tid < 224) {
        int pair = tid & 31, py = tid >> 5;          // py 0..6
        float s0 = 0.f, s1 = 0.f;
        #pragma unroll
        for (int px = 0; px < 7; px++) {
            const __half2* s = (const __half2*)&sc3[((2 * py) * 15 + 2 * px) * 32 + pair];
            __half2 m = __hmax2(__hmax2(s[0], s[32]), __hmax2(s[15 * 32], s[15 * 32 + 32]));
            float2 f = __half22float2(m);
            s0 += f.x; s1 += f.y;
        }
        sred[(py * 32 + pair) * 2]     = s0;
        sred[(py * 32 + pair) * 2 + 1] = s1;
    }
    __syncthreads();
    if (tid < 32) {
        float s0 = 0.f, s1 = 0.f;
        #pragma unroll
        for (int py = 0; py < 7; py++) {
            s0 += sred[(py * 32 + tid) * 2];
            s1 += sred[(py * 32 + tid) * 2 + 1];
        }
        g_avg[b * 128 + ochalf * 64 + 2 * tid]     = s0 * (1.f / 49.f);
        g_avg[b * 128 + ochalf * 64 + 2 * tid + 1] = s1 * (1.f / 49.f);
    }
}

// ---------------------------------------------------------------------------
// Launch 6: FC 128 -> 128 relu -> 5
// ---------------------------------------------------------------------------
__global__ void k_fc(const float* __restrict__ fw1, const float* __restrict__ fb1,
                     const float* __restrict__ fw2, const float* __restrict__ fb2,
                     float* __restrict__ out) {
    int b = blockIdx.x;
    int tid = threadIdx.x;
    __shared__ float sa[128], sh[128];
    sa[tid] = g_avg[b * 128 + tid];
    __syncthreads();
    float s = fb1[tid];
    const float* wr = fw1 + tid * 128;
    #pragma unroll 8
    for (int j = 0; j < 128; j++) s += wr[j] * sa[j];
    sh[tid] = s > 0.f ? s : 0.f;
    __syncthreads();
    if (tid < 5) {
        float o = fb2[tid];
        const float* wr2 = fw2 + tid * 128;
        #pragma unroll 8
        for (int j = 0; j < 128; j++) o += wr2[j] * sh[j];
        out[b * 5 + tid] = o;
    }
}

// ---------------------------------------------------------------------------
extern "C" void kernel_launch(void* const* d_in, const int* in_sizes, int n_in,
                              void* d_out, int out_size) {
    const int*   x   = (const int*)  d_in[0];
    const float* w1  = (const float*)d_in[1];
    const float* b1  = (const float*)d_in[2];
    const float* w2  = (const float*)d_in[3];
    const float* b2  = (const float*)d_in[4];
    const float* w3  = (const float*)d_in[5];
    const float* b3  = (const float*)d_in[6];
    const float* fw1 = (const float*)d_in[7];
    const float* fb1 = (const float*)d_in[8];
    const float* fw2 = (const float*)d_in[9];
    const float* fb2 = (const float*)d_in[10];
    float* out = (float*)d_out;

    cudaFuncSetAttribute(k_conv2_mma, cudaFuncAttributeMaxDynamicSharedMemorySize, C2_SMEM);
    cudaFuncSetAttribute(k_conv3_mma, cudaFuncAttributeMaxDynamicSharedMemorySize, C3_SMEM);

    k_setup<<<L1_GRID, 256>>>(x, w2, w3);                       // 1
    k_scatter1<<<NIMG, 256>>>(w1);                              // 2
    k_pool1<<<(NB * 961 * 16) / 256, 256>>>(b1);                // 3
    k_conv2_mma<<<dim3(NB, 2, 2), 256, C2_SMEM>>>(b2);          // 4 <- profiled
    k_conv3_mma<<<dim3(NB, 2), 256, C3_SMEM>>>(b3);             // 5
    k_fc<<<NB, 128>>>(fw1, fb1, fw2, fb2, out);                 // 6
}